// round 2
// baseline (speedup 1.0000x reference)
#include <cuda_runtime.h>

#define NB 16
#define NA 3
#define NM 32
#define NC 80
#define NH 80
#define NW 80
#define NHW (NH * NW)                 // 6400
#define CH (NA * (5 + NC) + NA * NM)  // 351
#define NE (NB * NA * NHW)            // 307200
#define TPB 256
#define EPT 4
#define EPB (TPB * EPT)               // 1024
#define NBLK (NE / EPB)               // 300
#define THRESH 0.05f
#define STRIDEF 8.0f
#define ROW (7 + NM)                  // 39

#define FLAG_AGG  (1ull << 62)
#define FLAG_PRE  (2ull << 62)

__device__ unsigned long long g_state[NBLK];

__global__ void init_kernel()
{
    int i = threadIdx.x;
    if (i < NBLK) g_state[i] = 0ull;
}

__global__ void __launch_bounds__(TPB)
fused_kernel(const float* __restrict__ in, const float* __restrict__ anchors,
             float* __restrict__ out, long long out_size)
{
    const int tid  = threadIdx.x;
    const int lane = tid & 31;
    const int wid  = tid >> 5;
    const int bid  = blockIdx.x;

    const int e0 = bid * EPB + tid * EPT;
    const int b  = e0 / (NA * NHW);
    const int r  = e0 - b * (NA * NHW);
    const int a  = r / NHW;
    const int p  = r - a * NHW;           // p % 4 == 0, 4 elems share (b,a), same grid row

    const float* base = in + ((size_t)b * CH + (size_t)a * (5 + NC)) * NHW + p;

    // ---- load box raw channels (float4 = 4 elements) ----
    float4 x0 = *(const float4*)(base + 0 * NHW);
    float4 y0 = *(const float4*)(base + 1 * NHW);
    float4 w0 = *(const float4*)(base + 2 * NHW);
    float4 h0 = *(const float4*)(base + 3 * NHW);
    float4 o0 = *(const float4*)(base + 4 * NHW);

    // ---- max-free softmax: s = sum(exp(x)), m/idx = running max/argmax ----
    float m0 = -1e30f, m1 = -1e30f, m2 = -1e30f, m3 = -1e30f;
    float s0 = 0.f, s1 = 0.f, s2 = 0.f, s3 = 0.f;
    int i0 = 0, i1 = 0, i2 = 0, i3 = 0;
    const float4* cb = (const float4*)(base + 5 * NHW);
#pragma unroll 8
    for (int c = 0; c < NC; ++c) {
        float4 x = cb[c * (NHW / 4)];
        s0 += __expf(x.x); if (x.x > m0) { m0 = x.x; i0 = c; }
        s1 += __expf(x.y); if (x.y > m1) { m1 = x.y; i1 = c; }
        s2 += __expf(x.z); if (x.z > m2) { m2 = x.z; i2 = c; }
        s3 += __expf(x.w); if (x.w > m3) { m3 = x.w; i3 = c; }
    }

    float score[4], clsv[4];
    bool keep[4];
    {
        float om[4] = { o0.x, o0.y, o0.z, o0.w };
        float mm[4] = { m0, m1, m2, m3 };
        float ss[4] = { s0, s1, s2, s3 };
        int   ii[4] = { i0, i1, i2, i3 };
#pragma unroll
        for (int i = 0; i < 4; ++i) {
            float obj = 1.0f / (1.0f + expf(-om[i]));   // accurate: threshold-critical
            score[i] = obj * __expf(mm[i]) / ss[i];
            clsv[i]  = (float)ii[i];
            keep[i]  = score[i] > THRESH;
        }
    }

    // ---- block scan of per-thread keep counts ----
    __shared__ int s_warp[TPB / 32];
    __shared__ int s_base;
    int kc = (int)keep[0] + (int)keep[1] + (int)keep[2] + (int)keep[3];
    int incl = kc;
#pragma unroll
    for (int d = 1; d < 32; d <<= 1) {
        int n = __shfl_up_sync(0xffffffffu, incl, d);
        if (lane >= d) incl += n;
    }
    if (lane == 31) s_warp[wid] = incl;
    __syncthreads();
    if (wid == 0) {
        int w = (lane < TPB / 32) ? s_warp[lane] : 0;
#pragma unroll
        for (int d = 1; d < TPB / 32; d <<= 1) {
            int n = __shfl_up_sync(0xffffffffu, w, d);
            if (lane >= d) w += n;
        }
        if (lane < TPB / 32) s_warp[lane] = w;
    }
    __syncthreads();
    const int texcl = (wid ? s_warp[wid - 1] : 0) + incl - kc;
    const int total = s_warp[TPB / 32 - 1];

    // ---- decoupled lookback (warp 0) ----
    if (wid == 0) {
        if (bid == 0) {
            if (lane == 0) {
                atomicExch(&g_state[0], FLAG_PRE | (unsigned)total);
                s_base = 0;
            }
        } else {
            if (lane == 0)
                atomicExch(&g_state[bid], FLAG_AGG | (unsigned)total);
            int excl = 0;
            int j = bid - 1;
            while (j >= 0) {
                int idx = j - lane;
                bool valid = idx >= 0;
                unsigned long long v;
                do {
                    v = valid ? atomicAdd(&g_state[idx], 0ull) : FLAG_PRE;
                } while (__any_sync(0xffffffffu, (v >> 62) == 0ull));
                unsigned pmask = __ballot_sync(0xffffffffu, (v >> 62) == 2ull);
                int cut = pmask ? (__ffs(pmask) - 1) : 32;
                unsigned add = (lane <= (cut < 31 ? cut : 31)) ? (unsigned)(v & 0xffffffffu) : 0u;
                excl += (int)__reduce_add_sync(0xffffffffu, add);
                if (cut < 32) break;
                j -= 32;
            }
            if (lane == 0) {
                atomicExch(&g_state[bid], FLAG_PRE | (unsigned)(excl + total));
                s_base = excl;
            }
        }
    }
    __syncthreads();
    const int gbase = s_base;

    if (kc == 0) return;

    // ---- decode boxes only for kept elements ----
    float aw = anchors[a * 2 + 0];
    float ah = anchors[a * 2 + 1];
    float amax = fmaxf(fmaxf(fmaxf(anchors[0], anchors[1]),
                             fmaxf(anchors[2], anchors[3])),
                       fmaxf(anchors[4], anchors[5]));
    float maxv = floorf(logf(1e35f / amax / STRIDEF));
    float linx = (float)(p % NW);
    float liny = (float)(p / NW);

    float xr[4] = { x0.x, x0.y, x0.z, x0.w };
    float yr[4] = { y0.x, y0.y, y0.z, y0.w };
    float wr[4] = { w0.x, w0.y, w0.z, w0.w };
    float hr[4] = { h0.x, h0.y, h0.z, h0.w };

    int rows[4];
    bool wok[4];
    {
        int rk = gbase + texcl;
#pragma unroll
        for (int i = 0; i < 4; ++i) {
            rows[i] = rk;
            if (keep[i]) ++rk;
            wok[i] = keep[i] && ((long long)rows[i] * ROW + ROW <= out_size);
        }
    }

#pragma unroll
    for (int i = 0; i < 4; ++i) {
        if (!wok[i]) continue;
        long long o = (long long)rows[i] * ROW;
        float xs = (1.0f / (1.0f + __expf(-xr[i])) + linx + (float)i) * STRIDEF;
        float ys = (1.0f / (1.0f + __expf(-yr[i])) + liny) * STRIDEF;
        float wv = __expf(fminf(wr[i], maxv)) * aw * STRIDEF;
        float hv = __expf(fminf(hr[i], maxv)) * ah * STRIDEF;
        out[o + 0] = (float)b;
        out[o + 1] = xs;
        out[o + 2] = ys;
        out[o + 3] = wv;
        out[o + 4] = hv;
        out[o + 5 + NM] = score[i];
        out[o + 6 + NM] = clsv[i];
    }

    // ---- mask-coefficient gather (float4 covers the thread's 4 elements) ----
    const float4* mrow = (const float4*)(in + ((size_t)b * CH + NA * (5 + NC) + (size_t)a * NM) * NHW + p);
#pragma unroll 8
    for (int mi = 0; mi < NM; ++mi) {
        float4 mv = mrow[mi * (NHW / 4)];
        float mvv[4] = { mv.x, mv.y, mv.z, mv.w };
#pragma unroll
        for (int i = 0; i < 4; ++i)
            if (wok[i]) out[(long long)rows[i] * ROW + 5 + mi] = mvv[i];
    }
}

extern "C" void kernel_launch(void* const* d_in, const int* in_sizes, int n_in,
                              void* d_out, int out_size)
{
    const float* in      = (const float*)d_in[0];
    const float* anchors = (const float*)d_in[1];
    float* out = (float*)d_out;

    init_kernel<<<1, 512>>>();
    fused_kernel<<<NBLK, TPB>>>(in, anchors, out, (long long)out_size);
}

// round 3
// speedup vs baseline: 1.1884x; 1.1884x over previous
#include <cuda_runtime.h>

#define NB 16
#define NA 3
#define NM 32
#define NC 80
#define NH 80
#define NW 80
#define NHW (NH * NW)                 // 6400
#define CH (NA * (5 + NC) + NA * NM)  // 351
#define NE (NB * NA * NHW)            // 307200
#define TPB 256
#define EPT 2
#define EPB (TPB * EPT)               // 512
#define NBLK (NE / EPB)               // 600
#define THRESH 0.05f
#define STRIDEF 8.0f
#define ROW (7 + NM)                  // 39

#define FLAG_AGG  (1ull << 62)
#define FLAG_PRE  (2ull << 62)

__device__ unsigned long long g_state[NBLK];

__global__ void init_kernel()
{
    int i = blockIdx.x * blockDim.x + threadIdx.x;
    if (i < NBLK) g_state[i] = 0ull;
}

__global__ void __launch_bounds__(TPB, 5)
fused_kernel(const float* __restrict__ in, const float* __restrict__ anchors,
             float* __restrict__ out, long long out_size)
{
    const int tid  = threadIdx.x;
    const int lane = tid & 31;
    const int wid  = tid >> 5;
    const int bid  = blockIdx.x;

    const int e0 = bid * EPB + tid * EPT;
    const int b  = e0 / (NA * NHW);
    const int r  = e0 - b * (NA * NHW);
    const int a  = r / NHW;
    const int p  = r - a * NHW;           // p % 2 == 0; both elems share (b,a), same grid row

    const float* base = in + ((size_t)b * CH + (size_t)a * (5 + NC)) * NHW + p;

    // ---- load box raw channels (float2 = 2 elements) ----
    float2 x0 = *(const float2*)(base + 0 * NHW);
    float2 y0 = *(const float2*)(base + 1 * NHW);
    float2 w0 = *(const float2*)(base + 2 * NHW);
    float2 h0 = *(const float2*)(base + 3 * NHW);
    float2 o0 = *(const float2*)(base + 4 * NHW);

    // ---- max-free softmax: s = sum(exp(x)); m/idx = running max/argmax ----
    float m0 = -1e30f, m1 = -1e30f;
    float s0 = 0.f, s1 = 0.f;
    int i0 = 0, i1 = 0;
    const float2* cb = (const float2*)(base + 5 * NHW);
#pragma unroll 8
    for (int c = 0; c < NC; ++c) {
        float2 x = cb[c * (NHW / 2)];
        s0 += __expf(x.x); if (x.x > m0) { m0 = x.x; i0 = c; }
        s1 += __expf(x.y); if (x.y > m1) { m1 = x.y; i1 = c; }
    }

    float score[EPT], clsv[EPT];
    bool keep[EPT];
    {
        float obj0 = 1.0f / (1.0f + expf(-o0.x));   // accurate: threshold-critical
        float obj1 = 1.0f / (1.0f + expf(-o0.y));
        score[0] = obj0 * __expf(m0) / s0;
        score[1] = obj1 * __expf(m1) / s1;
        clsv[0] = (float)i0;  clsv[1] = (float)i1;
        keep[0] = score[0] > THRESH;
        keep[1] = score[1] > THRESH;
    }

    // ---- block scan of per-thread keep counts ----
    __shared__ int s_warp[TPB / 32];
    __shared__ int s_base;
    int kc = (int)keep[0] + (int)keep[1];
    int incl = kc;
#pragma unroll
    for (int d = 1; d < 32; d <<= 1) {
        int n = __shfl_up_sync(0xffffffffu, incl, d);
        if (lane >= d) incl += n;
    }
    if (lane == 31) s_warp[wid] = incl;
    __syncthreads();
    if (wid == 0) {
        int w = (lane < TPB / 32) ? s_warp[lane] : 0;
#pragma unroll
        for (int d = 1; d < TPB / 32; d <<= 1) {
            int n = __shfl_up_sync(0xffffffffu, w, d);
            if (lane >= d) w += n;
        }
        if (lane < TPB / 32) s_warp[lane] = w;
    }
    __syncthreads();
    const int texcl = (wid ? s_warp[wid - 1] : 0) + incl - kc;
    const int total = s_warp[TPB / 32 - 1];

    // ---- decoupled lookback (warp 0) ----
    if (wid == 0) {
        if (bid == 0) {
            if (lane == 0) {
                atomicExch(&g_state[0], FLAG_PRE | (unsigned)total);
                s_base = 0;
            }
        } else {
            if (lane == 0)
                atomicExch(&g_state[bid], FLAG_AGG | (unsigned)total);
            int excl = 0;
            int j = bid - 1;
            while (j >= 0) {
                int idx = j - lane;
                bool valid = idx >= 0;
                unsigned long long v;
                do {
                    v = valid ? atomicAdd(&g_state[idx], 0ull) : FLAG_PRE;
                } while (__any_sync(0xffffffffu, (v >> 62) == 0ull));
                unsigned pmask = __ballot_sync(0xffffffffu, (v >> 62) == 2ull);
                int cut = pmask ? (__ffs(pmask) - 1) : 32;
                unsigned add = (lane <= (cut < 31 ? cut : 31)) ? (unsigned)(v & 0xffffffffu) : 0u;
                excl += (int)__reduce_add_sync(0xffffffffu, add);
                if (cut < 32) break;
                j -= 32;
            }
            if (lane == 0) {
                atomicExch(&g_state[bid], FLAG_PRE | (unsigned)(excl + total));
                s_base = excl;
            }
        }
    }
    __syncthreads();
    const int gbase = s_base;

    if (kc == 0) return;

    // ---- decode boxes only for kept elements ----
    float aw = anchors[a * 2 + 0];
    float ah = anchors[a * 2 + 1];
    float amax = fmaxf(fmaxf(fmaxf(anchors[0], anchors[1]),
                             fmaxf(anchors[2], anchors[3])),
                       fmaxf(anchors[4], anchors[5]));
    float maxv = floorf(logf(1e35f / amax / STRIDEF));
    float linx = (float)(p % NW);
    float liny = (float)(p / NW);

    float xr[EPT] = { x0.x, x0.y };
    float yr[EPT] = { y0.x, y0.y };
    float wr[EPT] = { w0.x, w0.y };
    float hr[EPT] = { h0.x, h0.y };

    int rows[EPT];
    bool wok[EPT];
    {
        int rk = gbase + texcl;
#pragma unroll
        for (int i = 0; i < EPT; ++i) {
            rows[i] = rk;
            if (keep[i]) ++rk;
            wok[i] = keep[i] && ((long long)rows[i] * ROW + ROW <= out_size);
        }
    }

#pragma unroll
    for (int i = 0; i < EPT; ++i) {
        if (!wok[i]) continue;
        long long o = (long long)rows[i] * ROW;
        float xs = (1.0f / (1.0f + __expf(-xr[i])) + linx + (float)i) * STRIDEF;
        float ys = (1.0f / (1.0f + __expf(-yr[i])) + liny) * STRIDEF;
        float wv = __expf(fminf(wr[i], maxv)) * aw * STRIDEF;
        float hv = __expf(fminf(hr[i], maxv)) * ah * STRIDEF;
        out[o + 0] = (float)b;
        out[o + 1] = xs;
        out[o + 2] = ys;
        out[o + 3] = wv;
        out[o + 4] = hv;
        out[o + 5 + NM] = score[i];
        out[o + 6 + NM] = clsv[i];
    }

    // ---- mask-coefficient gather (float2 covers the thread's 2 elements) ----
    const float2* mrow = (const float2*)(in + ((size_t)b * CH + NA * (5 + NC) + (size_t)a * NM) * NHW + p);
#pragma unroll 8
    for (int mi = 0; mi < NM; ++mi) {
        float2 mv = mrow[mi * (NHW / 2)];
        if (wok[0]) out[(long long)rows[0] * ROW + 5 + mi] = mv.x;
        if (wok[1]) out[(long long)rows[1] * ROW + 5 + mi] = mv.y;
    }
}

extern "C" void kernel_launch(void* const* d_in, const int* in_sizes, int n_in,
                              void* d_out, int out_size)
{
    const float* in      = (const float*)d_in[0];
    const float* anchors = (const float*)d_in[1];
    float* out = (float*)d_out;

    init_kernel<<<(NBLK + 255) / 256, 256>>>();
    fused_kernel<<<NBLK, TPB>>>(in, anchors, out, (long long)out_size);
}

// round 4
// speedup vs baseline: 1.3481x; 1.1344x over previous
#include <cuda_runtime.h>

#define NB 16
#define NA 3
#define NM 32
#define NC 80
#define NH 80
#define NW 80
#define NHW (NH * NW)                 // 6400
#define CH (NA * (5 + NC) + NA * NM)  // 351
#define NE (NB * NA * NHW)            // 307200
#define TPB 256
#define NBLK (NE / TPB)               // 1200
#define THRESH 0.05f
#define STRIDEF 8.0f
#define ROW (7 + NM)                  // 39

#define FLAG_AGG  (1ull << 62)
#define FLAG_PRE  (2ull << 62)

__device__ unsigned long long g_state[NBLK];

__global__ void init_kernel()
{
    int i = blockIdx.x * blockDim.x + threadIdx.x;
    if (i < NBLK) g_state[i] = 0ull;
}

__global__ void __launch_bounds__(TPB, 6)
fused_kernel(const float* __restrict__ in, const float* __restrict__ anchors,
             float* __restrict__ out, long long out_size)
{
    const int tid  = threadIdx.x;
    const int lane = tid & 31;
    const int wid  = tid >> 5;
    const int bid  = blockIdx.x;

    const int e = bid * TPB + tid;
    const int b = e / (NA * NHW);
    const int r = e - b * (NA * NHW);
    const int a = r / NHW;
    const int p = r - a * NHW;

    const float* base = in + ((size_t)b * CH + (size_t)a * (5 + NC)) * NHW + p;

    // ---- max-free softmax over NC logits: cls_max = exp(m)/sum(exp(x)) ----
    float m = -1e30f, s = 0.0f;
    int idx = 0;
    const float* cb = base + 5 * NHW;
#pragma unroll 10
    for (int c = 0; c < NC; ++c) {
        float x = __ldg(cb + c * NHW);
        s += __expf(x);
        if (x > m) { m = x; idx = c; }
    }

    // objectness: accurate exp (threshold-critical)
    float obj = 1.0f / (1.0f + expf(-__ldg(base + 4 * NHW)));
    float score = obj * __expf(m) / s;
    bool keep = score > THRESH;

    // ---- block-wide ordered rank of kept elements ----
    __shared__ int s_warp[TPB / 32];
    __shared__ int s_base;
    unsigned ball = __ballot_sync(0xffffffffu, keep);
    if (lane == 0) s_warp[wid] = __popc(ball);
    __syncthreads();
    if (wid == 0 && lane < TPB / 32) {
        int w = s_warp[lane];
#pragma unroll
        for (int d = 1; d < TPB / 32; d <<= 1) {
            int n = __shfl_up_sync(0xffu, w, d);
            if (lane >= d) w += n;
        }
        s_warp[lane] = w;   // inclusive warp-prefix
    }
    __syncthreads();
    const int total = s_warp[TPB / 32 - 1];
    const int texcl = (wid ? s_warp[wid - 1] : 0) + __popc(ball & ((1u << lane) - 1u));

    // ---- decoupled lookback (warp 0) ----
    if (wid == 0) {
        if (bid == 0) {
            if (lane == 0) {
                atomicExch(&g_state[0], FLAG_PRE | (unsigned)total);
                s_base = 0;
            }
        } else {
            if (lane == 0)
                atomicExch(&g_state[bid], FLAG_AGG | (unsigned)total);
            int excl = 0;
            int j = bid - 1;
            while (j >= 0) {
                int gidx = j - lane;
                bool valid = gidx >= 0;
                unsigned long long v;
                do {
                    v = valid ? atomicAdd(&g_state[gidx], 0ull) : FLAG_PRE;
                } while (__any_sync(0xffffffffu, (v >> 62) == 0ull));
                unsigned pmask = __ballot_sync(0xffffffffu, (v >> 62) == 2ull);
                int cut = pmask ? (__ffs(pmask) - 1) : 32;
                unsigned add = (lane <= (cut < 31 ? cut : 31)) ? (unsigned)(v & 0xffffffffu) : 0u;
                excl += (int)__reduce_add_sync(0xffffffffu, add);
                if (cut < 32) break;
                j -= 32;
            }
            if (lane == 0) {
                atomicExch(&g_state[bid], FLAG_PRE | (unsigned)(excl + total));
                s_base = excl;
            }
        }
    }
    __syncthreads();

    if (total == 0) return;

    const int row = s_base + texcl;
    const long long o = (long long)row * ROW;
    const bool wok = keep && (o + ROW <= out_size);

    if (wok) {
        // box channels loaded only now (shorter live ranges)
        float x0 = __ldg(base + 0 * NHW);
        float y0 = __ldg(base + 1 * NHW);
        float w0 = __ldg(base + 2 * NHW);
        float h0 = __ldg(base + 3 * NHW);

        float aw = anchors[a * 2 + 0];
        float ah = anchors[a * 2 + 1];
        float amax = fmaxf(fmaxf(fmaxf(anchors[0], anchors[1]),
                                 fmaxf(anchors[2], anchors[3])),
                           fmaxf(anchors[4], anchors[5]));
        float maxv = floorf(logf(1e35f / amax / STRIDEF));

        float xs = (1.0f / (1.0f + __expf(-x0)) + (float)(p % NW)) * STRIDEF;
        float ys = (1.0f / (1.0f + __expf(-y0)) + (float)(p / NW)) * STRIDEF;
        float wv = __expf(fminf(w0, maxv)) * aw * STRIDEF;
        float hv = __expf(fminf(h0, maxv)) * ah * STRIDEF;

        out[o + 0] = (float)b;
        out[o + 1] = xs;
        out[o + 2] = ys;
        out[o + 3] = wv;
        out[o + 4] = hv;
        out[o + 5 + NM] = score;
        out[o + 6 + NM] = (float)idx;
    }

    // ---- mask-coefficient gather (kept threads only; coalesced across p) ----
    const float* mb = in + ((size_t)b * CH + NA * (5 + NC) + (size_t)a * NM) * NHW + p;
    if (wok) {
#pragma unroll 8
        for (int mi = 0; mi < NM; ++mi)
            out[o + 5 + mi] = __ldg(mb + mi * NHW);
    }
}

extern "C" void kernel_launch(void* const* d_in, const int* in_sizes, int n_in,
                              void* d_out, int out_size)
{
    const float* in      = (const float*)d_in[0];
    const float* anchors = (const float*)d_in[1];
    float* out = (float*)d_out;

    init_kernel<<<(NBLK + 255) / 256, 256>>>();
    fused_kernel<<<NBLK, TPB>>>(in, anchors, out, (long long)out_size);
}